// round 7
// baseline (speedup 1.0000x reference)
#include <cuda_runtime.h>

#define NN    50000
#define DIN   128
#define DOUT  64
#define EE    800000
#define GTILE 64          // nodes per GEMM block
#define SHPAD 132         // padded sH row stride (breaks bank conflicts)
#define NB1   49          // scan1 blocks (49*1024 >= NN)

// ---------------------------------------------------------------------------
// Device scratch
// ---------------------------------------------------------------------------
__device__ float  g_X[NN * DOUT];     // projected features
__device__ int    g_cnt[NN];          // degree counters -> scatter cursors
__device__ int    g_rowptr[NN + 1];   // CSR row offsets
__device__ int    g_scan[NN];         // block-local exclusive scan
__device__ int    g_bsum[NB1];        // per-block totals
__device__ float2 g_edge[EE];         // CSR (col as int bits, val)

// ---------------------------------------------------------------------------
// Packed fp32x2 helpers (sm_10x FFMA2 path — PTX only)
// ---------------------------------------------------------------------------
__device__ __forceinline__ unsigned long long ffma2(
    unsigned long long a, unsigned long long b, unsigned long long c) {
    unsigned long long d;
    asm("fma.rn.f32x2 %0, %1, %2, %3;" : "=l"(d) : "l"(a), "l"(b), "l"(c));
    return d;
}
__device__ __forceinline__ unsigned long long pack2(float lo, float hi) {
    unsigned long long r;
    asm("mov.b64 %0, {%1, %2};" : "=l"(r) : "f"(lo), "f"(hi));
    return r;
}
__device__ __forceinline__ void unpack2(unsigned long long v, float& lo, float& hi) {
    asm("mov.b64 {%0, %1}, %2;" : "=f"(lo), "=f"(hi) : "l"(v));
}

// ---------------------------------------------------------------------------
// CSR build
// ---------------------------------------------------------------------------
__global__ void zero_cnt_kernel() {
    int i = blockIdx.x * blockDim.x + threadIdx.x;
    if (i < NN / 4)
        reinterpret_cast<int4*>(g_cnt)[i] = make_int4(0, 0, 0, 0);
}

// histogram: 4 edges per thread (vectorized rows load)
__global__ void hist_kernel(const int* __restrict__ rows) {
    int t = blockIdx.x * blockDim.x + threadIdx.x;
    if (t < EE / 4) {
        int4 r = reinterpret_cast<const int4*>(rows)[t];
        atomicAdd(&g_cnt[r.x], 1);
        atomicAdd(&g_cnt[r.y], 1);
        atomicAdd(&g_cnt[r.z], 1);
        atomicAdd(&g_cnt[r.w], 1);
    }
}

// scan1: per-block exclusive scan of 1024 degrees + block total
__global__ __launch_bounds__(1024) void scan1_kernel() {
    __shared__ int wsum[32];
    int tid  = threadIdx.x;
    int i    = blockIdx.x * 1024 + tid;
    int lane = tid & 31, warp = tid >> 5;

    int orig = (i < NN) ? g_cnt[i] : 0;
    int v = orig;
    #pragma unroll
    for (int o = 1; o < 32; o <<= 1) {
        int n = __shfl_up_sync(0xffffffffu, v, o);
        if (lane >= o) v += n;
    }
    if (lane == 31) wsum[warp] = v;
    __syncthreads();
    if (warp == 0) {
        int s = wsum[lane];
        #pragma unroll
        for (int o = 1; o < 32; o <<= 1) {
            int n = __shfl_up_sync(0xffffffffu, s, o);
            if (lane >= o) s += n;
        }
        wsum[lane] = s;
    }
    __syncthreads();
    int base = (warp > 0) ? wsum[warp - 1] : 0;
    if (i < NN) g_scan[i] = base + v - orig;
    if (tid == 1023) g_bsum[blockIdx.x] = wsum[31];
}

// scan3: each block redundantly scans the 49 block totals (warp 0), then
// finalizes rowptr and seeds scatter cursors. (scan2 kernel folded in.)
__global__ __launch_bounds__(256) void scan3_kernel() {
    __shared__ int sOff[NB1];
    int tid = threadIdx.x;

    if (tid < 32) {
        int a = (2 * tid     < NB1) ? g_bsum[2 * tid]     : 0;
        int b = (2 * tid + 1 < NB1) ? g_bsum[2 * tid + 1] : 0;
        int s = a + b;
        int incl = s;
        #pragma unroll
        for (int o = 1; o < 32; o <<= 1) {
            int n = __shfl_up_sync(0xffffffffu, incl, o);
            if (tid >= o) incl += n;
        }
        int excl = incl - s;
        if (2 * tid     < NB1) sOff[2 * tid]     = excl;
        if (2 * tid + 1 < NB1) sOff[2 * tid + 1] = excl + a;
    }
    __syncthreads();

    int i = blockIdx.x * 256 + tid;
    if (i < NN) {
        int r = g_scan[i] + sOff[i >> 10];
        g_rowptr[i] = r;
        g_cnt[i]    = r;
    }
    if (i == 0) g_rowptr[NN] = EE;
}

// scatter: 4 edges per thread, one packed 8B store per edge
__global__ void scatter_kernel(const int* __restrict__ rows,
                               const int* __restrict__ cols,
                               const float* __restrict__ vals) {
    int t = blockIdx.x * blockDim.x + threadIdx.x;
    if (t < EE / 4) {
        int4   r = reinterpret_cast<const int4*>(rows)[t];
        int4   c = reinterpret_cast<const int4*>(cols)[t];
        float4 v = reinterpret_cast<const float4*>(vals)[t];
        int p0 = atomicAdd(&g_cnt[r.x], 1);
        int p1 = atomicAdd(&g_cnt[r.y], 1);
        int p2 = atomicAdd(&g_cnt[r.z], 1);
        int p3 = atomicAdd(&g_cnt[r.w], 1);
        g_edge[p0] = make_float2(__int_as_float(c.x), v.x);
        g_edge[p1] = make_float2(__int_as_float(c.y), v.y);
        g_edge[p2] = make_float2(__int_as_float(c.z), v.z);
        g_edge[p3] = make_float2(__int_as_float(c.w), v.w);
    }
}

// ---------------------------------------------------------------------------
// Fused L2-normalize + BN(eval) + Linear(128->64)+bias -> g_X
//   64 nodes / block, 128 threads; each thread: 8 nodes x 4 cols via FFMA2
//   (4 node-pairs x 4 cols = 16 fma.rn.f32x2 per k).
// ---------------------------------------------------------------------------
__global__ __launch_bounds__(128) void fused_gemm_kernel(
    const float* __restrict__ H,
    const float* __restrict__ gamma,
    const float* __restrict__ beta,
    const float* __restrict__ mean,
    const float* __restrict__ var,
    const float* __restrict__ W,
    const float* __restrict__ bias)
{
    __shared__ float sW[DIN * DOUT];        // 32 KB
    __shared__ float sH[GTILE * SHPAD];     // 33.8 KB
    __shared__ float sA[DIN];
    __shared__ float sC[DIN];
    __shared__ float sInv[GTILE];

    const int tid    = threadIdx.x;
    const int node0  = blockIdx.x * GTILE;
    const int nvalid = min(GTILE, NN - node0);

    // Stage W (float4, coalesced)
    #pragma unroll
    for (int i = tid; i < DIN * DOUT / 4; i += 128)
        reinterpret_cast<float4*>(sW)[i] =
            reinterpret_cast<const float4*>(W)[i];

    // BN per-feature constants
    {
        float a = gamma[tid] * rsqrtf(var[tid] + 1e-5f);
        sA[tid] = a;
        sC[tid] = beta[tid] - mean[tid] * a;
    }

    // Stage H tile
    #pragma unroll
    for (int i4 = tid; i4 < GTILE * (DIN / 4); i4 += 128) {
        int r = i4 >> 5;
        int c = (i4 & 31) * 4;
        float4 v = (r < nvalid)
            ? reinterpret_cast<const float4*>(H)[(node0 + r) * (DIN / 4) + (c >> 2)]
            : make_float4(1.f, 0.f, 0.f, 0.f);
        *reinterpret_cast<float4*>(&sH[r * SHPAD + c]) = v;
    }
    __syncthreads();

    // Row L2 norms: 2 threads per row
    {
        int r = tid >> 1, l = tid & 1;
        float ss = 0.f;
        #pragma unroll
        for (int i = 0; i < 16; i++) {
            float4 v = *reinterpret_cast<float4*>(&sH[r * SHPAD + l * 64 + i * 4]);
            ss += v.x * v.x + v.y * v.y + v.z * v.z + v.w * v.w;
        }
        ss += __shfl_xor_sync(0xffffffffu, ss, 1);
        if (l == 0) sInv[r] = 1.0f / fmaxf(sqrtf(ss), 1e-12f);
    }
    __syncthreads();

    // normalize + BN in place
    #pragma unroll
    for (int i4 = tid; i4 < GTILE * (DIN / 4); i4 += 128) {
        int r = i4 >> 5;
        int c = (i4 & 31) * 4;
        float inv = sInv[r];
        float4 h  = *reinterpret_cast<float4*>(&sH[r * SHPAD + c]);
        float4 a  = *reinterpret_cast<float4*>(&sA[c]);
        float4 cc = *reinterpret_cast<float4*>(&sC[c]);
        h.x = fmaf(h.x * inv, a.x, cc.x);
        h.y = fmaf(h.y * inv, a.y, cc.y);
        h.z = fmaf(h.z * inv, a.z, cc.z);
        h.w = fmaf(h.w * inv, a.w, cc.w);
        *reinterpret_cast<float4*>(&sH[r * SHPAD + c]) = h;
    }
    __syncthreads();

    // GEMM: thread = (8 nodes as 4 pairs, 4 cols), packed f32x2 FMAs
    const int jg = tid & 15;          // 16 col groups * 4 = 64 cols
    const int ng = tid >> 4;          // 8 node groups * 8 = 64 nodes
    const int n0 = ng * 8;
    const int j0 = jg * 4;

    unsigned long long acc[4][4];
    #pragma unroll
    for (int p = 0; p < 4; p++)
        #pragma unroll
        for (int j = 0; j < 4; j++) acc[p][j] = 0ull;

    #pragma unroll 4
    for (int k = 0; k < DIN; k++) {
        float4 w = *reinterpret_cast<float4*>(&sW[k * DOUT + j0]);
        unsigned long long w0 = pack2(w.x, w.x);
        unsigned long long w1 = pack2(w.y, w.y);
        unsigned long long w2 = pack2(w.z, w.z);
        unsigned long long w3 = pack2(w.w, w.w);
        #pragma unroll
        for (int p = 0; p < 4; p++) {
            float hlo = sH[(n0 + 2 * p)     * SHPAD + k];
            float hhi = sH[(n0 + 2 * p + 1) * SHPAD + k];
            unsigned long long hp = pack2(hlo, hhi);
            acc[p][0] = ffma2(hp, w0, acc[p][0]);
            acc[p][1] = ffma2(hp, w1, acc[p][1]);
            acc[p][2] = ffma2(hp, w2, acc[p][2]);
            acc[p][3] = ffma2(hp, w3, acc[p][3]);
        }
    }

    float4 bb = *reinterpret_cast<const float4*>(&bias[j0]);
    #pragma unroll
    for (int p = 0; p < 4; p++) {
        float4 lo, hi;
        unpack2(acc[p][0], lo.x, hi.x);
        unpack2(acc[p][1], lo.y, hi.y);
        unpack2(acc[p][2], lo.z, hi.z);
        unpack2(acc[p][3], lo.w, hi.w);
        lo.x += bb.x; lo.y += bb.y; lo.z += bb.z; lo.w += bb.w;
        hi.x += bb.x; hi.y += bb.y; hi.z += bb.z; hi.w += bb.w;
        int na = n0 + 2 * p, nb = na + 1;
        if (na < nvalid)
            *reinterpret_cast<float4*>(&g_X[(node0 + na) * DOUT + j0]) = lo;
        if (nb < nvalid)
            *reinterpret_cast<float4*>(&g_X[(node0 + nb) * DOUT + j0]) = hi;
    }
}

// ---------------------------------------------------------------------------
// Row-parallel SpMM + LeakyReLU: 16 threads per row, float4 per lane.
// Unrolled by 2 for extra MLP.
// ---------------------------------------------------------------------------
__global__ __launch_bounds__(256) void spmm_leaky_kernel(float* __restrict__ out)
{
    int gid  = blockIdx.x * 256 + threadIdx.x;
    int row  = gid >> 4;
    if (row >= NN) return;
    int lane = gid & 15;
    int c0   = lane * 4;

    int s = g_rowptr[row];
    int e = g_rowptr[row + 1];

    float4 a0 = make_float4(0.f, 0.f, 0.f, 0.f);
    float4 a1 = make_float4(0.f, 0.f, 0.f, 0.f);

    int p = s;
    for (; p + 1 < e; p += 2) {
        float2 ev0 = g_edge[p];
        float2 ev1 = g_edge[p + 1];
        float4 x0 = *reinterpret_cast<const float4*>(
            &g_X[__float_as_int(ev0.x) * DOUT + c0]);
        float4 x1 = *reinterpret_cast<const float4*>(
            &g_X[__float_as_int(ev1.x) * DOUT + c0]);
        a0.x = fmaf(ev0.y, x0.x, a0.x); a0.y = fmaf(ev0.y, x0.y, a0.y);
        a0.z = fmaf(ev0.y, x0.z, a0.z); a0.w = fmaf(ev0.y, x0.w, a0.w);
        a1.x = fmaf(ev1.y, x1.x, a1.x); a1.y = fmaf(ev1.y, x1.y, a1.y);
        a1.z = fmaf(ev1.y, x1.z, a1.z); a1.w = fmaf(ev1.y, x1.w, a1.w);
    }
    if (p < e) {
        float2 ev = g_edge[p];
        float4 x = *reinterpret_cast<const float4*>(
            &g_X[__float_as_int(ev.x) * DOUT + c0]);
        a0.x = fmaf(ev.y, x.x, a0.x); a0.y = fmaf(ev.y, x.y, a0.y);
        a0.z = fmaf(ev.y, x.z, a0.z); a0.w = fmaf(ev.y, x.w, a0.w);
    }

    float4 a;
    a.x = a0.x + a1.x; a.y = a0.y + a1.y;
    a.z = a0.z + a1.z; a.w = a0.w + a1.w;

    a.x = a.x >= 0.f ? a.x : 0.01f * a.x;
    a.y = a.y >= 0.f ? a.y : 0.01f * a.y;
    a.z = a.z >= 0.f ? a.z : 0.01f * a.z;
    a.w = a.w >= 0.f ? a.w : 0.01f * a.w;

    *reinterpret_cast<float4*>(&out[row * DOUT + c0]) = a;
}

// ---------------------------------------------------------------------------
extern "C" void kernel_launch(void* const* d_in, const int* in_sizes, int n_in,
                              void* d_out, int out_size) {
    const float* H     = (const float*)d_in[0];
    const int*   rows  = (const int*)  d_in[1];
    const int*   cols  = (const int*)  d_in[2];
    const float* vals  = (const float*)d_in[3];
    const float* gamma = (const float*)d_in[4];
    const float* beta  = (const float*)d_in[5];
    const float* rmean = (const float*)d_in[6];
    const float* rvar  = (const float*)d_in[7];
    const float* W     = (const float*)d_in[8];
    const float* b     = (const float*)d_in[9];
    float* out = (float*)d_out;

    // CSR build
    zero_cnt_kernel<<<(NN / 4 + 255) / 256, 256>>>();
    hist_kernel<<<(EE / 4 + 255) / 256, 256>>>(rows);
    scan1_kernel<<<NB1, 1024>>>();
    scan3_kernel<<<(NN + 255) / 256, 256>>>();
    scatter_kernel<<<(EE / 4 + 255) / 256, 256>>>(rows, cols, vals);

    // Dense part
    fused_gemm_kernel<<<(NN + GTILE - 1) / GTILE, 128>>>(H, gamma, beta,
                                                         rmean, rvar, W, b);

    // Sparse aggregation + activation
    spmm_leaky_kernel<<<(NN * 16 + 255) / 256, 256>>>(out);
}